// round 3
// baseline (speedup 1.0000x reference)
#include <cuda_runtime.h>
#include <cuda_fp16.h>
#include <mma.h>
#include <cstdint>
#include <math.h>

using namespace nvcuda;

// Problem constants
#define TSTEPS 512
#define BATCH  512
#define IDIM   128
#define HDIM   512
#define KACT   640   // IDIM + HDIM

// Partitioning: 8 batch-groups x 16 CTAs = 128 CTAs (1 per SM, all resident)
#define NGROUPS 8
#define GCTAS   16
#define NCTA    (NGROUPS*GCTAS)
#define MB      64    // batch rows per group
#define HS      32    // h-columns per CTA
#define NGATE   128   // gate columns per CTA (HS x 4 gates)
#define NTHREADS 256

// SMEM padding (bank-conflict avoidance)
#define WPAD 648      // weight row stride (halfs): 648*2B=1296B -> +4 banks/row
#define FPAD 40       // A-stage / fc-weight row stride (halfs)
#define GPAD 132      // gates staging row stride (floats)

#define SMEM_BYTES (128*WPAD*2 + 128*FPAD*2 + 2*64*FPAD*2 + 64*GPAD*4 + 64*32*4 + 128*4)
// = 165888 + 10240 + 10240 + 33792 + 8192 + 512 = 228864 bytes

// Global state (activations double-buffered by step parity; hi/lo fp16 split terms)
__device__ __align__(16) __half g_act[2][2][BATCH][KACT];   // [parity][term][row][col]
__device__ float g_fcpart[NGROUPS*GCTAS*MB*IDIM];           // fc partial sums
__device__ unsigned g_bar[NGROUPS];                          // monotonic group barrier counters

__device__ __forceinline__ void group_barrier(int gid, unsigned target) {
    if (threadIdx.x == 0) {
        __threadfence();                 // release: publish my global writes
        atomicAdd(&g_bar[gid], 1u);
        while (*((volatile unsigned*)&g_bar[gid]) < target) { __nanosleep(40); }
        __threadfence();                 // acquire: see others' global writes
    }
    __syncthreads();
}

__device__ __forceinline__ float sigmoidf_(float z) { return 1.0f / (1.0f + expf(-z)); }

__global__ void __launch_bounds__(NTHREADS, 1) decoder_kernel(
    const float* __restrict__ x,    const float* __restrict__ h0,
    const float* __restrict__ c0,   const float* __restrict__ W_ih,
    const float* __restrict__ W_hh, const float* __restrict__ b_ih,
    const float* __restrict__ b_hh, const float* __restrict__ fc_W,
    const float* __restrict__ fc_b, float* __restrict__ out)
{
    extern __shared__ unsigned char smem_raw[];
    __half* Wsm  = (__half*)smem_raw;               // [128][WPAD]  gate-weight slice
    __half* FCsm = Wsm + 128*WPAD;                  // [128][FPAD]  fc weight K-slice (fc_W[n][hs..hs+31])
    __half* Ast  = FCsm + 128*FPAD;                 // [2][64][FPAD] A staging (gates) / h split (fc)
    float*  gsm  = (float*)(Ast + 2*64*FPAD);       // [64][GPAD]   gate accum staging
    float*  csm  = gsm + 64*GPAD;                   // [64][32]     cell state (resident all steps)
    float*  bsm  = csm + 64*32;                     // [128]        fused gate bias

    const int tid  = threadIdx.x;
    const int gid  = blockIdx.x / GCTAS;
    const int rk   = blockIdx.x % GCTAS;
    const int row0 = gid * MB;
    const int hs   = rk * HS;

    const int wid = tid >> 5;
    const int wr  = wid >> 2;     // 0..1 : warp row (32 batch rows each)
    const int wc  = wid & 3;      // 0..3 : warp col (32 output cols each)

    // ---------------- init: weights -> SMEM (once, reused 512 steps) ----------------
    for (int idx = tid; idx < 128*KACT; idx += NTHREADS) {
        int r = idx / KACT, k = idx - r*KACT;
        int q = r >> 5, j = r & 31;
        int grow = q*HDIM + hs + j;                  // global gate row (i,f,g,o chunks)
        float v = (k < IDIM) ? W_ih[grow*IDIM + k] : W_hh[grow*HDIM + (k - IDIM)];
        Wsm[r*WPAD + k] = __float2half_rn(v);
    }
    for (int idx = tid; idx < 128*HS; idx += NTHREADS) {
        int n = idx / HS, k = idx - n*HS;
        FCsm[n*FPAD + k] = __float2half_rn(fc_W[n*HDIM + hs + k]);
    }
    for (int r = tid; r < 128; r += NTHREADS) {
        int q = r >> 5, j = r & 31;
        int grow = q*HDIM + hs + j;
        bsm[r] = b_ih[grow] + b_hh[grow];
    }
    for (int idx = tid; idx < MB*HS; idx += NTHREADS) {
        int m = idx >> 5, j = idx & 31;
        csm[m*HS + j] = c0[(row0+m)*HDIM + hs + j];
    }
    // act buffer parity 0: this CTA seeds inp cols [rk*8, rk*8+8) and h cols [hs, hs+32)
    for (int idx = tid; idx < MB*8; idx += NTHREADS) {
        int m = idx >> 3, cc = rk*8 + (idx & 7);
        float v = x[(TSTEPS-1)*BATCH*IDIM + (row0+m)*IDIM + cc];
        __half hi = __float2half_rn(v);
        __half lo = __float2half_rn(v - __half2float(hi));
        g_act[0][0][row0+m][cc] = hi;
        g_act[0][1][row0+m][cc] = lo;
    }
    for (int idx = tid; idx < MB*HS; idx += NTHREADS) {
        int m = idx >> 5, j = idx & 31;
        float v = h0[(row0+m)*HDIM + hs + j];
        __half hi = __float2half_rn(v);
        __half lo = __float2half_rn(v - __half2float(hi));
        g_act[0][0][row0+m][IDIM+hs+j] = hi;
        g_act[0][1][row0+m][IDIM+hs+j] = lo;
    }

    unsigned phase = 1;
    group_barrier(gid, phase * GCTAS);

    const int lm  = tid >> 2;        // 0..63 staging row
    const int seg = tid & 3;         // 0..3  staging 8-half segment

    // ---------------- 512 sequential steps ----------------
    for (int t = 0; t < TSTEPS; t++) {
        const int pr = t & 1;        // read parity
        const int pn = pr ^ 1;       // write parity

        // ===== gates GEMM: [64 x 128] += A2[64 x 1280] @ Wsm^T =====
        wmma::fragment<wmma::accumulator, 16, 16, 16, float> acc[2][2];
        #pragma unroll
        for (int i = 0; i < 2; i++)
            #pragma unroll
            for (int j = 0; j < 2; j++)
                wmma::fill_fragment(acc[i][j], 0.0f);

        // stage chunk 0
        {
            const uint4* src = reinterpret_cast<const uint4*>(&g_act[pr][0][row0+lm][seg*8]);
            *reinterpret_cast<uint4*>(&Ast[(0*64 + lm)*FPAD + seg*8]) = *src;
        }
        __syncthreads();

        #pragma unroll 4
        for (int cc = 0; cc < 40; cc++) {
            uint4 pref;
            const bool has_next = (cc + 1 < 40);
            if (has_next) {
                int nterm = (cc+1) / 20;
                int nkk   = ((cc+1) % 20) * 32;
                pref = *reinterpret_cast<const uint4*>(&g_act[pr][nterm][row0+lm][nkk + seg*8]);
            }
            const __half* Ab = Ast + (cc & 1) * 64 * FPAD;
            const int kk = (cc % 20) * 32;
            #pragma unroll
            for (int kt = 0; kt < 2; kt++) {
                wmma::fragment<wmma::matrix_a, 16, 16, 16, __half, wmma::row_major> af[2];
                wmma::fragment<wmma::matrix_b, 16, 16, 16, __half, wmma::col_major> bf[2];
                #pragma unroll
                for (int i = 0; i < 2; i++)
                    wmma::load_matrix_sync(af[i], Ab + (wr*32 + i*16)*FPAD + kt*16, FPAD);
                #pragma unroll
                for (int j = 0; j < 2; j++)
                    wmma::load_matrix_sync(bf[j], Wsm + (wc*32 + j*16)*WPAD + kk + kt*16, WPAD);
                #pragma unroll
                for (int i = 0; i < 2; i++)
                    #pragma unroll
                    for (int j = 0; j < 2; j++)
                        wmma::mma_sync(acc[i][j], af[i], bf[j], acc[i][j]);
            }
            if (has_next) {
                int b = (cc + 1) & 1;
                *reinterpret_cast<uint4*>(&Ast[(b*64 + lm)*FPAD + seg*8]) = pref;
            }
            __syncthreads();
        }

        #pragma unroll
        for (int i = 0; i < 2; i++)
            #pragma unroll
            for (int j = 0; j < 2; j++)
                wmma::store_matrix_sync(&gsm[(wr*32 + i*16)*GPAD + wc*32 + j*16],
                                        acc[i][j], GPAD, wmma::mem_row_major);
        __syncthreads();

        // ===== pointwise LSTM + write h_new (global, next parity) + local h split =====
        #pragma unroll
        for (int it = 0; it < (MB*HS)/NTHREADS; it++) {
            int idx = tid + it*NTHREADS;
            int m = idx >> 5, j = idx & 31;
            float zi = gsm[m*GPAD +       j] + bsm[      j];
            float zf = gsm[m*GPAD + 32  + j] + bsm[32  + j];
            float zg = gsm[m*GPAD + 64  + j] + bsm[64  + j];
            float zo = gsm[m*GPAD + 96  + j] + bsm[96  + j];
            float c  = csm[m*HS + j];
            float ig = sigmoidf_(zi);
            float fg = sigmoidf_(zf);
            float gg = tanhf(zg);
            float og = sigmoidf_(zo);
            float cn = fg*c + ig*gg;
            float hn = og * tanhf(cn);
            csm[m*HS + j] = cn;
            __half hi = __float2half_rn(hn);
            __half lo = __float2half_rn(hn - __half2float(hi));
            g_act[pn][0][row0+m][IDIM+hs+j] = hi;
            g_act[pn][1][row0+m][IDIM+hs+j] = lo;
            Ast[(0*64 + m)*FPAD + j] = hi;       // local split for fc K-slice
            Ast[(1*64 + m)*FPAD + j] = lo;
        }
        __syncthreads();

        // ===== fc partial: [64 x 128] = h_slice[64 x 32](hi+lo) @ fc_W[:, hs:hs+32]^T =====
        wmma::fragment<wmma::accumulator, 16, 16, 16, float> pacc[2][2];
        #pragma unroll
        for (int i = 0; i < 2; i++)
            #pragma unroll
            for (int j = 0; j < 2; j++)
                wmma::fill_fragment(pacc[i][j], 0.0f);
        #pragma unroll
        for (int tt = 0; tt < 2; tt++) {
            #pragma unroll
            for (int kt = 0; kt < 2; kt++) {
                wmma::fragment<wmma::matrix_a, 16, 16, 16, __half, wmma::row_major> af[2];
                wmma::fragment<wmma::matrix_b, 16, 16, 16, __half, wmma::col_major> bf[2];
                #pragma unroll
                for (int i = 0; i < 2; i++)
                    wmma::load_matrix_sync(af[i], Ast + (tt*64 + wr*32 + i*16)*FPAD + kt*16, FPAD);
                #pragma unroll
                for (int j = 0; j < 2; j++)
                    wmma::load_matrix_sync(bf[j], FCsm + (wc*32 + j*16)*FPAD + kt*16, FPAD);
                #pragma unroll
                for (int i = 0; i < 2; i++)
                    #pragma unroll
                    for (int j = 0; j < 2; j++)
                        wmma::mma_sync(pacc[i][j], af[i], bf[j], pacc[i][j]);
            }
        }
        {
            float* base = &g_fcpart[((gid*GCTAS + rk)*MB)*IDIM];
            #pragma unroll
            for (int i = 0; i < 2; i++)
                #pragma unroll
                for (int j = 0; j < 2; j++)
                    wmma::store_matrix_sync(base + (wr*32 + i*16)*IDIM + wc*32 + j*16,
                                            pacc[i][j], IDIM, wmma::mem_row_major);
        }

        phase++;
        group_barrier(gid, phase * GCTAS);   // barrier A: fc partials + h_new published

        // ===== finalize fc cols [rk*8, rk*8+8): reduce 16 partials, activation, feedback =====
        #pragma unroll
        for (int it = 0; it < (MB*8)/NTHREADS; it++) {
            int idx = tid + it*NTHREADS;
            int m = idx >> 3, n = rk*8 + (idx & 7);
            float z = fc_b[n];
            #pragma unroll
            for (int s = 0; s < GCTAS; s++)
                z += g_fcpart[((gid*GCTAS + s)*MB + m)*IDIM + n];
            float y = tanhf(0.5f * z);       // == 2*sigmoid(z) - 1
            out[(TSTEPS-1-t)*BATCH*IDIM + (row0+m)*IDIM + n] = y;
            __half hi = __float2half_rn(y);
            __half lo = __float2half_rn(y - __half2float(hi));
            g_act[pn][0][row0+m][n] = hi;
            g_act[pn][1][row0+m][n] = lo;
        }

        phase++;
        group_barrier(gid, phase * GCTAS);   // barrier B: next-step inputs published
    }
}

extern "C" void kernel_launch(void* const* d_in, const int* in_sizes, int n_in,
                              void* d_out, int out_size)
{
    const float* x    = (const float*)d_in[0];
    // d_in[1] = enc_hiddens : unused by the reference recursion
    const float* h0   = (const float*)d_in[2];
    const float* c0   = (const float*)d_in[3];
    const float* W_ih = (const float*)d_in[4];
    const float* W_hh = (const float*)d_in[5];
    const float* b_ih = (const float*)d_in[6];
    const float* b_hh = (const float*)d_in[7];
    const float* fc_W = (const float*)d_in[8];
    const float* fc_b = (const float*)d_in[9];
    float* out = (float*)d_out;

    cudaFuncSetAttribute(decoder_kernel, cudaFuncAttributeMaxDynamicSharedMemorySize, SMEM_BYTES);

    // Reset group-barrier counters every launch (graph-capturable memset node)
    void* barp = nullptr;
    cudaGetSymbolAddress(&barp, g_bar);
    cudaMemsetAsync(barp, 0, sizeof(unsigned) * NGROUPS);

    decoder_kernel<<<NCTA, NTHREADS, SMEM_BYTES>>>(x, h0, c0, W_ih, W_hh,
                                                   b_ih, b_hh, fc_W, fc_b, out);
}

// round 4
// speedup vs baseline: 1.9956x; 1.9956x over previous
#include <cuda_runtime.h>
#include <cuda_fp16.h>
#include <mma.h>
#include <cstdint>
#include <math.h>

using namespace nvcuda;

// Problem constants
#define TSTEPS 512
#define BATCH  512
#define IDIM   128
#define HDIM   512
#define KACT   640   // reordered: cols [0,512)=h, [512,640)=inp

// Partitioning: 8 batch-groups x 16 CTAs = 128 CTAs (1 per SM, all resident)
#define NGROUPS 8
#define GCTAS   16
#define NCTA    (NGROUPS*GCTAS)
#define MB      64
#define HS      32
#define NTHREADS 256

// SMEM padding / tiling
#define WPAD 648      // weight row stride (halfs)
#define FPAD 40       // Hloc / fc-weight row stride (halfs)
#define GPAD 132      // gates staging row stride (floats)
#define APAD 72       // A-stage row stride (halfs): 144B -> rows land 16B apart mod 128
#define CHUNK 64      // K columns per staged chunk (per term)
#define NCHUNK 10
#define HCHUNK 8      // chunks [0,8) = h region, [8,10) = inp region

// SMEM layout (bytes):
//  Wsm  128*WPAD*2          = 165888
//  FCsm 128*FPAD*2          =  10240
//  R    max(gsm 64*GPAD*4=33792, Ast 2*2*64*APAD*2=36864) = 36864  (aliased)
//  Hloc 2*64*FPAD*2         =  10240
//  csm  64*32*4             =   8192
//  bsm  128*4               =    512
#define SMEM_BYTES (165888 + 10240 + 36864 + 10240 + 8192 + 512)   // 231936

// Global state
__device__ __align__(16) __half g_act[2][2][BATCH][KACT];   // [parity][term][row][col]
__device__ float g_fcpart[NGROUPS*GCTAS*MB*IDIM];
__device__ unsigned g_bar[NGROUPS];

__device__ __forceinline__ void bar_arrive(int gid) {
    if (threadIdx.x == 0) {
        __threadfence();                 // release my global writes
        atomicAdd(&g_bar[gid], 1u);
    }
}
__device__ __forceinline__ void bar_wait(int gid, unsigned target) {
    if (threadIdx.x == 0) {
        while (*((volatile unsigned*)&g_bar[gid]) < target) { __nanosleep(20); }
        __threadfence();                 // acquire others' global writes
    }
    __syncthreads();
}

__device__ __forceinline__ float sigmoidf_(float z) { return 1.0f / (1.0f + expf(-z)); }

// Staged-chunk MMA over chunks [c_begin, c_end). Accumulates A(hi+lo) @ W^T.
// B fragments loaded ONCE per k-tile and reused for both hi/lo terms.
__device__ __forceinline__ void mma_chunks(
    wmma::fragment<wmma::accumulator, 16, 16, 16, float> (&acc)[2][2],
    const __half* __restrict__ gact_p,   // &g_act[p][0][0][0]; term stride = BATCH*KACT
    __half* __restrict__ Ast,            // [2 buf][2 term][64][APAD]
    const __half* __restrict__ Wsm,
    int row0, int wr, int wc, int lm, int seg,
    int c_begin, int c_end)
{
    const size_t TSTRIDE = (size_t)BATCH * KACT;
    const __half* src_row0 = gact_p + (size_t)(row0 + lm) * KACT;
    const __half* src_row1 = src_row0 + TSTRIDE;
    __half* dst_row = Ast + lm * APAD + seg * 16;

    // stage chunk c_begin into buf 0
    {
        int c0 = c_begin * CHUNK + seg * 16;
        const uint4* s0 = reinterpret_cast<const uint4*>(src_row0 + c0);
        const uint4* s1 = reinterpret_cast<const uint4*>(src_row1 + c0);
        uint4 a0 = s0[0], a1 = s0[1], b0 = s1[0], b1 = s1[1];
        uint4* d0 = reinterpret_cast<uint4*>(dst_row);
        uint4* d1 = reinterpret_cast<uint4*>(dst_row + 64 * APAD);
        d0[0] = a0; d0[1] = a1; d1[0] = b0; d1[1] = b1;
    }
    __syncthreads();

    int buf = 0;
    for (int cc = c_begin; cc < c_end; cc++) {
        uint4 p0, p1, p2, p3;
        const bool hn = (cc + 1 < c_end);
        if (hn) {
            int c0 = (cc + 1) * CHUNK + seg * 16;
            const uint4* s0 = reinterpret_cast<const uint4*>(src_row0 + c0);
            const uint4* s1 = reinterpret_cast<const uint4*>(src_row1 + c0);
            p0 = s0[0]; p1 = s0[1]; p2 = s1[0]; p3 = s1[1];
        }

        const __half* Ab = Ast + buf * (2 * 64 * APAD);
        const int kbase = cc * CHUNK;
        #pragma unroll
        for (int kt = 0; kt < 4; kt++) {
            wmma::fragment<wmma::matrix_b, 16, 16, 16, __half, wmma::col_major> bf[2];
            #pragma unroll
            for (int j = 0; j < 2; j++)
                wmma::load_matrix_sync(bf[j], Wsm + (wc*32 + j*16)*WPAD + kbase + kt*16, WPAD);
            #pragma unroll
            for (int term = 0; term < 2; term++) {
                const __half* At = Ab + term * 64 * APAD;
                #pragma unroll
                for (int i = 0; i < 2; i++) {
                    wmma::fragment<wmma::matrix_a, 16, 16, 16, __half, wmma::row_major> af;
                    wmma::load_matrix_sync(af, At + (wr*32 + i*16)*APAD + kt*16, APAD);
                    #pragma unroll
                    for (int j = 0; j < 2; j++)
                        wmma::mma_sync(acc[i][j], af, bf[j], acc[i][j]);
                }
            }
        }

        if (hn) {
            buf ^= 1;
            __half* dr = Ast + buf * (2 * 64 * APAD) + lm * APAD + seg * 16;
            uint4* d0 = reinterpret_cast<uint4*>(dr);
            uint4* d1 = reinterpret_cast<uint4*>(dr + 64 * APAD);
            d0[0] = p0; d0[1] = p1; d1[0] = p2; d1[1] = p3;
        }
        __syncthreads();
    }
}

__global__ void __launch_bounds__(NTHREADS, 1) decoder_kernel(
    const float* __restrict__ x,    const float* __restrict__ h0,
    const float* __restrict__ c0,   const float* __restrict__ W_ih,
    const float* __restrict__ W_hh, const float* __restrict__ b_ih,
    const float* __restrict__ b_hh, const float* __restrict__ fc_W,
    const float* __restrict__ fc_b, float* __restrict__ out)
{
    extern __shared__ unsigned char smem_raw[];
    __half* Wsm  = (__half*)smem_raw;                        // [128][WPAD]
    __half* FCsm = Wsm + 128*WPAD;                           // [128][FPAD]
    __half* Ast  = FCsm + 128*FPAD;                          // R: [2][2][64][APAD] (aliases gsm)
    float*  gsm  = (float*)Ast;                              // R: [64][GPAD]
    __half* Hloc = (__half*)(smem_raw + 165888 + 10240 + 36864); // [2][64][FPAD]
    float*  csm  = (float*)(Hloc + 2*64*FPAD);               // [64][32]
    float*  bsm  = csm + 64*32;                              // [128]

    const int tid  = threadIdx.x;
    const int gid  = blockIdx.x / GCTAS;
    const int rk   = blockIdx.x % GCTAS;
    const int row0 = gid * MB;
    const int hs   = rk * HS;

    const int wid = tid >> 5;
    const int wr  = wid >> 2;     // 0..1
    const int wc  = wid & 3;      // 0..3
    const int lm  = tid >> 2;     // 0..63
    const int seg = tid & 3;      // 0..3

    // ---------------- init (once) ----------------
    // Weights, K-reordered: col k<512 -> W_hh[.,k]; k>=512 -> W_ih[., k-512]
    for (int idx = tid; idx < 128*KACT; idx += NTHREADS) {
        int r = idx / KACT, k = idx - r*KACT;
        int q = r >> 5, j = r & 31;
        int grow = q*HDIM + hs + j;
        float v = (k < HDIM) ? W_hh[grow*HDIM + k] : W_ih[grow*IDIM + (k - HDIM)];
        Wsm[r*WPAD + k] = __float2half_rn(v);
    }
    for (int idx = tid; idx < 128*HS; idx += NTHREADS) {
        int n = idx / HS, k = idx - n*HS;
        FCsm[n*FPAD + k] = __float2half_rn(fc_W[n*HDIM + hs + k]);
    }
    for (int r = tid; r < 128; r += NTHREADS) {
        int q = r >> 5, j = r & 31;
        bsm[r] = b_ih[q*HDIM + hs + j] + b_hh[q*HDIM + hs + j];
    }
    for (int idx = tid; idx < MB*HS; idx += NTHREADS) {
        int m = idx >> 5, j = idx & 31;
        csm[m*HS + j] = c0[(row0+m)*HDIM + hs + j];
    }
    // seed g_act parity 0: h at cols [hs,hs+32), inp at cols [512+rk*8, ...)
    for (int idx = tid; idx < MB*HS; idx += NTHREADS) {
        int m = idx >> 5, j = idx & 31;
        float v = h0[(row0+m)*HDIM + hs + j];
        __half hi = __float2half_rn(v);
        __half lo = __float2half_rn(v - __half2float(hi));
        g_act[0][0][row0+m][hs+j] = hi;
        g_act[0][1][row0+m][hs+j] = lo;
    }
    for (int idx = tid; idx < MB*8; idx += NTHREADS) {
        int m = idx >> 3, ccol = rk*8 + (idx & 7);
        float v = x[(TSTEPS-1)*BATCH*IDIM + (row0+m)*IDIM + ccol];
        __half hi = __float2half_rn(v);
        __half lo = __float2half_rn(v - __half2float(hi));
        g_act[0][0][row0+m][HDIM+ccol] = hi;
        g_act[0][1][row0+m][HDIM+ccol] = lo;
    }

    unsigned tgt = GCTAS;
    bar_arrive(gid);
    bar_wait(gid, tgt);     // seeds visible group-wide

    // ---------------- prologue: gates(0) ----------------
    {
        wmma::fragment<wmma::accumulator, 16, 16, 16, float> acc[2][2];
        #pragma unroll
        for (int i = 0; i < 2; i++)
            #pragma unroll
            for (int j = 0; j < 2; j++)
                wmma::fill_fragment(acc[i][j], 0.0f);
        mma_chunks(acc, &g_act[0][0][0][0], Ast, Wsm, row0, wr, wc, lm, seg, 0, NCHUNK);
        #pragma unroll
        for (int i = 0; i < 2; i++)
            #pragma unroll
            for (int j = 0; j < 2; j++)
                wmma::store_matrix_sync(&gsm[(wr*32 + i*16)*GPAD + wc*32 + j*16],
                                        acc[i][j], GPAD, wmma::mem_row_major);
        __syncthreads();
    }

    // ---------------- 512 sequential steps ----------------
    for (int t = 0; t < TSTEPS; t++) {
        const int pn = (t + 1) & 1;          // parity written this step / read by gates(t+1)
        const bool more = (t < TSTEPS - 1);

        // ===== pointwise LSTM: gsm -> h_new (global pn + Hloc) =====
        #pragma unroll
        for (int it = 0; it < (MB*HS)/NTHREADS; it++) {
            int idx = tid + it*NTHREADS;
            int m = idx >> 5, j = idx & 31;
            float zi = gsm[m*GPAD +      j] + bsm[     j];
            float zf = gsm[m*GPAD + 32 + j] + bsm[32 + j];
            float zg = gsm[m*GPAD + 64 + j] + bsm[64 + j];
            float zo = gsm[m*GPAD + 96 + j] + bsm[96 + j];
            float c  = csm[m*HS + j];
            float ig = sigmoidf_(zi);
            float fg = sigmoidf_(zf);
            float gg = tanhf(zg);
            float og = sigmoidf_(zo);
            float cn = fg*c + ig*gg;
            float hn = og * tanhf(cn);
            csm[m*HS + j] = cn;
            __half hi = __float2half_rn(hn);
            __half lo = __float2half_rn(hn - __half2float(hi));
            g_act[pn][0][row0+m][hs+j] = hi;
            g_act[pn][1][row0+m][hs+j] = lo;
            Hloc[(0*64 + m)*FPAD + j] = hi;
            Hloc[(1*64 + m)*FPAD + j] = lo;
        }
        __syncthreads();   // Hloc ready; gsm dead (R reusable after barrier)

        // ===== fc partial: [64 x 128] = (h_hi+h_lo)[64x32] @ fc_W_slice^T =====
        {
            wmma::fragment<wmma::accumulator, 16, 16, 16, float> pacc[2][2];
            #pragma unroll
            for (int i = 0; i < 2; i++)
                #pragma unroll
                for (int j = 0; j < 2; j++)
                    wmma::fill_fragment(pacc[i][j], 0.0f);
            #pragma unroll
            for (int tt = 0; tt < 2; tt++) {
                #pragma unroll
                for (int kt = 0; kt < 2; kt++) {
                    wmma::fragment<wmma::matrix_b, 16, 16, 16, __half, wmma::col_major> bf[2];
                    #pragma unroll
                    for (int j = 0; j < 2; j++)
                        wmma::load_matrix_sync(bf[j], FCsm + (wc*32 + j*16)*FPAD + kt*16, FPAD);
                    #pragma unroll
                    for (int i = 0; i < 2; i++) {
                        wmma::fragment<wmma::matrix_a, 16, 16, 16, __half, wmma::row_major> af;
                        wmma::load_matrix_sync(af, Hloc + (tt*64 + wr*32 + i*16)*FPAD + kt*16, FPAD);
                        #pragma unroll
                        for (int j = 0; j < 2; j++)
                            wmma::mma_sync(pacc[i][j], af, bf[j], pacc[i][j]);
                    }
                }
            }
            float* base = &g_fcpart[((gid*GCTAS + rk)*MB)*IDIM];
            #pragma unroll
            for (int i = 0; i < 2; i++)
                #pragma unroll
                for (int j = 0; j < 2; j++)
                    wmma::store_matrix_sync(base + (wr*32 + i*16)*IDIM + wc*32 + j*16,
                                            pacc[i][j], IDIM, wmma::mem_row_major);
        }

        bar_arrive(gid);                 // A: h_new + fc partials published
        tgt += GCTAS;
        bar_wait(gid, tgt);              // (only exposed barrier; symmetric skew)

        // ===== finalize fc cols [rk*8, rk*8+8): reduce, activate, feedback =====
        #pragma unroll
        for (int it = 0; it < (MB*8)/NTHREADS; it++) {
            int idx = tid + it*NTHREADS;
            int m = idx >> 3, n = rk*8 + (idx & 7);
            float z = fc_b[n];
            #pragma unroll
            for (int s = 0; s < GCTAS; s++)
                z += g_fcpart[((gid*GCTAS + s)*MB + m)*IDIM + n];
            float y = tanhf(0.5f * z);   // == 2*sigmoid(z) - 1
            out[(TSTEPS-1-t)*BATCH*IDIM + (row0+m)*IDIM + n] = y;
            __half hi = __float2half_rn(y);
            __half lo = __float2half_rn(y - __half2float(hi));
            g_act[pn][0][row0+m][HDIM+n] = hi;
            g_act[pn][1][row0+m][HDIM+n] = lo;
        }

        bar_arrive(gid);                 // B: inp(t+1) published
        tgt += GCTAS;

        if (more) {
            // ===== gates(t+1): part1 over h chunks (hidden slack for barrier B) =====
            wmma::fragment<wmma::accumulator, 16, 16, 16, float> acc[2][2];
            #pragma unroll
            for (int i = 0; i < 2; i++)
                #pragma unroll
                for (int j = 0; j < 2; j++)
                    wmma::fill_fragment(acc[i][j], 0.0f);
            const __half* gp = &g_act[pn][0][0][0];
            mma_chunks(acc, gp, Ast, Wsm, row0, wr, wc, lm, seg, 0, HCHUNK);

            bar_wait(gid, tgt);          // B: should be satisfied already

            // part2 over inp chunks
            mma_chunks(acc, gp, Ast, Wsm, row0, wr, wc, lm, seg, HCHUNK, NCHUNK);

            #pragma unroll
            for (int i = 0; i < 2; i++)
                #pragma unroll
                for (int j = 0; j < 2; j++)
                    wmma::store_matrix_sync(&gsm[(wr*32 + i*16)*GPAD + wc*32 + j*16],
                                            acc[i][j], GPAD, wmma::mem_row_major);
            __syncthreads();
        }
    }
}

extern "C" void kernel_launch(void* const* d_in, const int* in_sizes, int n_in,
                              void* d_out, int out_size)
{
    const float* x    = (const float*)d_in[0];
    // d_in[1] = enc_hiddens : unused by the reference recursion
    const float* h0   = (const float*)d_in[2];
    const float* c0   = (const float*)d_in[3];
    const float* W_ih = (const float*)d_in[4];
    const float* W_hh = (const float*)d_in[5];
    const float* b_ih = (const float*)d_in[6];
    const float* b_hh = (const float*)d_in[7];
    const float* fc_W = (const float*)d_in[8];
    const float* fc_b = (const float*)d_in[9];
    float* out = (float*)d_out;

    cudaFuncSetAttribute(decoder_kernel, cudaFuncAttributeMaxDynamicSharedMemorySize, SMEM_BYTES);

    // Reset group-barrier counters every replay (captured memset node)
    void* barp = nullptr;
    cudaGetSymbolAddress(&barp, g_bar);
    cudaMemsetAsync(barp, 0, sizeof(unsigned) * NGROUPS);

    decoder_kernel<<<NCTA, NTHREADS, SMEM_BYTES>>>(x, h0, c0, W_ih, W_hh,
                                                   b_ih, b_hh, fc_W, fc_b, out);
}